// round 2
// baseline (speedup 1.0000x reference)
#include <cuda_runtime.h>
#include <cuda_fp8.h>
#include <cstdint>

// ============================================================================
// y[b,s,o] = 4 * sum_i e4m3(x[b,s,i]*0.5) * W_e4m3[o,i]  + bias[o]
// M = 16384, N = 4096, K = 4096, fp32 out.
// Plain-target (sm_103, no 'a') path: mma.sync m16n8k32 e4m3 + ldmatrix + cp.async
// ============================================================================

#define DI __device__ __forceinline__

// ---------------- device scratch --------------------------------------------
__device__ uint8_t g_Aq[16384u * 4096u];   // 64MB quantized activations (e4m3)
__device__ uint8_t g_Wq[4096u * 4096u];    // 16MB weight as e4m3 bytes
__device__ int     g_wflag;                // 1 if weight buffer is fp32

// ---------------- helpers ---------------------------------------------------
DI uint32_t smem_u32(const void* p) {
    uint32_t a;
    asm("{ .reg .u64 t; cvta.to.shared.u64 t, %1; cvt.u32.u64 %0, t; }"
        : "=r"(a) : "l"(p));
    return a;
}
DI void cp_async16(uint32_t dst, const void* src) {
    asm volatile("cp.async.cg.shared.global [%0], [%1], 16;" :: "r"(dst), "l"(src));
}
DI void cp_commit() { asm volatile("cp.async.commit_group;" ::: "memory"); }
template <int N> DI void cp_wait() {
    asm volatile("cp.async.wait_group %0;" :: "n"(N) : "memory");
}
DI void ldmatrix4(uint32_t& r0, uint32_t& r1, uint32_t& r2, uint32_t& r3, uint32_t a) {
    asm volatile("ldmatrix.sync.aligned.m8n8.x4.shared.b16 {%0,%1,%2,%3}, [%4];"
                 : "=r"(r0), "=r"(r1), "=r"(r2), "=r"(r3) : "r"(a));
}
DI void mma_e4m3(float& c0, float& c1, float& c2, float& c3,
                 uint32_t a0, uint32_t a1, uint32_t a2, uint32_t a3,
                 uint32_t b0, uint32_t b1) {
    asm volatile(
        "mma.sync.aligned.m16n8k32.row.col.f32.e4m3.e4m3.f32 "
        "{%0,%1,%2,%3}, {%4,%5,%6,%7}, {%8,%9}, {%0,%1,%2,%3};"
        : "+f"(c0), "+f"(c1), "+f"(c2), "+f"(c3)
        : "r"(a0), "r"(a1), "r"(a2), "r"(a3), "r"(b0), "r"(b1));
}

// SMEM tile layout: rows of 64 bytes (BK), 16B units swizzled so that both
// the cp.async store pattern and ldmatrix 8-row reads are conflict-free:
// unit slot within 128B line = (row&1)*4 + (col ^ ((row>>1)&3)) -> all distinct.
DI uint32_t swz(int row, int col16) {
    return (uint32_t)(row * 64 + ((col16 ^ ((row >> 1) & 3)) << 4));
}

// ============================================================================
// Kernel 1: quantize activations  e4m3(x * 0.5)
// ============================================================================
__global__ void quant_act(const float4* __restrict__ in, int n4) {
    uint32_t* out = reinterpret_cast<uint32_t*>(g_Aq);
    int i = blockIdx.x * blockDim.x + threadIdx.x;
    int stride = gridDim.x * blockDim.x;
    for (; i < n4; i += stride) {
        float4 v = in[i];
        __nv_fp8x2_storage_t p0 = __nv_cvt_float2_to_fp8x2(
            make_float2(v.x * 0.5f, v.y * 0.5f), __NV_SATFINITE, __NV_E4M3);
        __nv_fp8x2_storage_t p1 = __nv_cvt_float2_to_fp8x2(
            make_float2(v.z * 0.5f, v.w * 0.5f), __NV_SATFINITE, __NV_E4M3);
        out[i] = (uint32_t)p0 | ((uint32_t)p1 << 16);
    }
}

// ============================================================================
// Kernel 2: weight dtype detect + normalize to e4m3 bytes
// fp32 weights: all finite & |x| <= 448. Raw e4m3 bytes reinterpreted as fp32
// fail this with overwhelming probability over 256 values.
// ============================================================================
__global__ void detect_wdtype(const float* __restrict__ w) {
    if (blockIdx.x == 0 && threadIdx.x == 0) {
        int ok = 1;
        for (int i = 0; i < 256; i++) {
            float x = w[i];
            if (!(fabsf(x) <= 448.0f)) { ok = 0; break; }
        }
        g_wflag = ok;
    }
}

__global__ void prep_w(const void* __restrict__ w, int n) {
    int flag = g_wflag;
    int idx = blockIdx.x * blockDim.x + threadIdx.x;
    int stride = gridDim.x * blockDim.x;
    if (flag) {
        const float4* wf = (const float4*)w;
        uint32_t* o = reinterpret_cast<uint32_t*>(g_Wq);
        for (int i = idx; i < n / 4; i += stride) {
            float4 v = wf[i];
            __nv_fp8x2_storage_t p0 = __nv_cvt_float2_to_fp8x2(
                make_float2(v.x, v.y), __NV_SATFINITE, __NV_E4M3);
            __nv_fp8x2_storage_t p1 = __nv_cvt_float2_to_fp8x2(
                make_float2(v.z, v.w), __NV_SATFINITE, __NV_E4M3);
            o[i] = (uint32_t)p0 | ((uint32_t)p1 << 16);
        }
    } else {
        const uint4* wb = (const uint4*)w;
        uint4* o = reinterpret_cast<uint4*>(g_Wq);
        for (int i = idx; i < n / 16; i += stride) o[i] = wb[i];
    }
}

// ============================================================================
// Kernel 3: FP8 GEMM (legacy mma.sync path)
//   CTA tile 256(M) x 128(N), BK = 64, 4-stage cp.async pipeline.
//   8 warps, warp tile 64x64 (wm in 0..3 along M, wn in 0..1 along N).
// ============================================================================
#define BM 256
#define BN 128
#define BK 64
#define KDIM 4096
#define NDIM 4096
#define MDIM 16384
#define KCHUNKS (KDIM / BK)          // 64
#define STAGES 4
#define NTHREADS 256

#define A_BYTES (BM * BK)            // 16384
#define B_BYTES (BN * BK)            // 8192
#define STAGE_BYTES (A_BYTES + B_BYTES)
#define SM_TOTAL (STAGES * STAGE_BYTES)   // 98304

DI void load_stage(uint32_t sb, int stage, const uint8_t* __restrict__ Ag,
                   const uint8_t* __restrict__ Bg, int ck, int tid) {
    uint32_t As = sb + stage * STAGE_BYTES;
    uint32_t Bs = As + A_BYTES;
    int col = tid & 3;            // 16B segment within 64B row
    int row0 = tid >> 2;          // 0..63
    const uint8_t* ag = Ag + (size_t)ck * BK + col * 16;
    const uint8_t* bg = Bg + (size_t)ck * BK + col * 16;
#pragma unroll
    for (int i = 0; i < BM / 64; i++) {
        int row = row0 + i * 64;
        cp_async16(As + swz(row, col), ag + (size_t)row * KDIM);
    }
#pragma unroll
    for (int i = 0; i < BN / 64; i++) {
        int row = row0 + i * 64;
        cp_async16(Bs + swz(row, col), bg + (size_t)row * KDIM);
    }
}

__global__ void __launch_bounds__(NTHREADS)
gemm_kernel(const float* __restrict__ bias, float* __restrict__ out) {
    extern __shared__ char smem[];
    uint32_t sb = smem_u32(smem);
    int tid = (int)threadIdx.x;
    int wid = tid >> 5;
    int lid = tid & 31;
    int wm = wid & 3;                 // M dir: 4 warps * 64 rows
    int wn = wid >> 2;                // N dir: 2 warps * 64 cols
    int tm = blockIdx.y;              // M tile
    int tn = blockIdx.x;              // N tile

    const uint8_t* Ag = g_Aq + (size_t)tm * BM * KDIM;
    const uint8_t* Bg = g_Wq + (size_t)tn * BN * KDIM;

    float acc[4][8][4];
#pragma unroll
    for (int mi = 0; mi < 4; mi++)
#pragma unroll
        for (int ni = 0; ni < 8; ni++)
#pragma unroll
            for (int r = 0; r < 4; r++) acc[mi][ni][r] = 0.0f;

    // lane-derived ldmatrix source coordinates
    int a_row_l = (lid & 7) + ((lid >> 3) & 1) * 8;   // 0..15 within m16 tile
    int a_half  = lid >> 4;                            // 16B half of k32
    int b_row_l = (lid & 7) + ((lid >> 4) & 1) * 8;   // 0..15 within n16 pair
    int b_half  = (lid >> 3) & 1;                      // 16B half of k32

    // prologue
#pragma unroll
    for (int s = 0; s < STAGES - 1; s++) {
        load_stage(sb, s, Ag, Bg, s, tid);
        cp_commit();
    }

    for (int ck = 0; ck < KCHUNKS; ck++) {
        int pf = ck + STAGES - 1;
        if (pf < KCHUNKS) load_stage(sb, pf & (STAGES - 1), Ag, Bg, pf, tid);
        cp_commit();
        cp_wait<STAGES - 2>();
        __syncthreads();

        uint32_t As = sb + (ck & (STAGES - 1)) * STAGE_BYTES;
        uint32_t Bs = As + A_BYTES;

#pragma unroll
        for (int ks = 0; ks < 2; ks++) {
            uint32_t a[4][4];
            uint32_t b[8][2];
#pragma unroll
            for (int mi = 0; mi < 4; mi++) {
                int row = wm * 64 + mi * 16 + a_row_l;
                int col16 = ks * 2 + a_half;
                ldmatrix4(a[mi][0], a[mi][1], a[mi][2], a[mi][3], As + swz(row, col16));
            }
#pragma unroll
            for (int np = 0; np < 4; np++) {
                int n = wn * 64 + np * 16 + b_row_l;
                int col16 = ks * 2 + b_half;
                ldmatrix4(b[2 * np][0], b[2 * np][1], b[2 * np + 1][0], b[2 * np + 1][1],
                          Bs + swz(n, col16));
            }
#pragma unroll
            for (int mi = 0; mi < 4; mi++)
#pragma unroll
                for (int ni = 0; ni < 8; ni++)
                    mma_e4m3(acc[mi][ni][0], acc[mi][ni][1], acc[mi][ni][2], acc[mi][ni][3],
                             a[mi][0], a[mi][1], a[mi][2], a[mi][3],
                             b[ni][0], b[ni][1]);
        }
        __syncthreads();
    }

    // Epilogue: out = acc*4 + bias
    int qrow = lid >> 2;                 // 0..7
    int qcol = (lid & 3) * 2;            // 0,2,4,6
    int m0 = tm * BM + wm * 64 + qrow;
    int n0 = tn * BN + wn * 64 + qcol;
#pragma unroll
    for (int mi = 0; mi < 4; mi++) {
#pragma unroll
        for (int ni = 0; ni < 8; ni++) {
            int n = n0 + ni * 8;
            float b0 = __ldg(bias + n);
            float b1 = __ldg(bias + n + 1);
            int mA = m0 + mi * 16;
            int mB = mA + 8;
            float2 v0 = make_float2(acc[mi][ni][0] * 4.0f + b0,
                                    acc[mi][ni][1] * 4.0f + b1);
            float2 v1 = make_float2(acc[mi][ni][2] * 4.0f + b0,
                                    acc[mi][ni][3] * 4.0f + b1);
            *reinterpret_cast<float2*>(out + (size_t)mA * NDIM + n) = v0;
            *reinterpret_cast<float2*>(out + (size_t)mB * NDIM + n) = v1;
        }
    }
}

// ============================================================================
// Host launch
// ============================================================================
extern "C" void kernel_launch(void* const* d_in, const int* in_sizes, int n_in,
                              void* d_out, int out_size) {
    const float* input = nullptr;
    const void*  weight = nullptr;
    const float* bias = nullptr;
    for (int i = 0; i < n_in; i++) {
        if (in_sizes[i] == 4 * 4096 * 4096)  input = (const float*)d_in[i];
        else if (in_sizes[i] == 4096 * 4096) weight = d_in[i];
        else if (in_sizes[i] == 4096)        bias = (const float*)d_in[i];
    }
    if (!input)  input  = (const float*)d_in[0];
    if (!weight) weight = d_in[1];
    if (!bias)   bias   = (const float*)d_in[2];
    float* out = (float*)d_out;

    // 1) quantize activations
    int n4 = (4 * 4096 * 4096) / 4;
    quant_act<<<8192, 256>>>((const float4*)input, n4);

    // 2) weight dtype detect + normalize to e4m3 bytes
    detect_wdtype<<<1, 1>>>((const float*)weight);
    prep_w<<<2048, 256>>>(weight, 4096 * 4096);

    // 3) GEMM + epilogue
    static bool attr_set = false;
    if (!attr_set) {
        cudaFuncSetAttribute(gemm_kernel,
                             cudaFuncAttributeMaxDynamicSharedMemorySize, SM_TOTAL);
        attr_set = true;
    }
    dim3 grid(NDIM / BN, MDIM / BM);   // (32, 64)
    gemm_kernel<<<grid, NTHREADS, SM_TOTAL>>>(bias, out);
}

// round 3
// speedup vs baseline: 1.1651x; 1.1651x over previous
#include <cuda_runtime.h>
#include <cuda_fp8.h>
#include <cstdint>

// ============================================================================
// y[b,s,o] = 4 * sum_i e4m3(x[b,s,i]*0.5) * W_e4m3[o,i]  + bias[o]
// M = 16384, N = 4096, K = 4096, fp32 out.
// Plain-target path: mma.sync m16n8k32 e4m3 + ldmatrix + cp.async
// R3: 512 thr / warp tile 64x32 (regs ~120 -> 16 resident warps), BK=128,
//     3 stages, single __syncthreads per K-chunk.
// ============================================================================

#define DI __device__ __forceinline__

// ---------------- device scratch --------------------------------------------
__device__ uint8_t g_Aq[16384u * 4096u];   // 64MB quantized activations (e4m3)
__device__ uint8_t g_Wq[4096u * 4096u];    // 16MB weight as e4m3 bytes
__device__ int     g_wflag;                // 1 if weight buffer is fp32

// ---------------- helpers ---------------------------------------------------
DI uint32_t smem_u32(const void* p) {
    uint32_t a;
    asm("{ .reg .u64 t; cvta.to.shared.u64 t, %1; cvt.u32.u64 %0, t; }"
        : "=r"(a) : "l"(p));
    return a;
}
DI void cp_async16(uint32_t dst, const void* src) {
    asm volatile("cp.async.cg.shared.global [%0], [%1], 16;" :: "r"(dst), "l"(src));
}
DI void cp_commit() { asm volatile("cp.async.commit_group;" ::: "memory"); }
template <int N> DI void cp_wait() {
    asm volatile("cp.async.wait_group %0;" :: "n"(N) : "memory");
}
DI void ldmatrix4(uint32_t& r0, uint32_t& r1, uint32_t& r2, uint32_t& r3, uint32_t a) {
    asm volatile("ldmatrix.sync.aligned.m8n8.x4.shared.b16 {%0,%1,%2,%3}, [%4];"
                 : "=r"(r0), "=r"(r1), "=r"(r2), "=r"(r3) : "r"(a));
}
DI void mma_e4m3(float& c0, float& c1, float& c2, float& c3,
                 uint32_t a0, uint32_t a1, uint32_t a2, uint32_t a3,
                 uint32_t b0, uint32_t b1) {
    asm volatile(
        "mma.sync.aligned.m16n8k32.row.col.f32.e4m3.e4m3.f32 "
        "{%0,%1,%2,%3}, {%4,%5,%6,%7}, {%8,%9}, {%0,%1,%2,%3};"
        : "+f"(c0), "+f"(c1), "+f"(c2), "+f"(c3)
        : "r"(a0), "r"(a1), "r"(a2), "r"(a3), "r"(b0), "r"(b1));
}

// 128B rows, 8 x 16B units, swizzled: unit' = col16 ^ (row & 7).
// Conflict-free for cp.async row-wise stores and 8-row ldmatrix reads.
DI uint32_t swz(int row, int col16) {
    return (uint32_t)(row * 128 + ((col16 ^ (row & 7)) << 4));
}

// ============================================================================
// Kernel 1: quantize activations  e4m3(x * 0.5)
// ============================================================================
__global__ void quant_act(const float4* __restrict__ in, int n4) {
    uint32_t* out = reinterpret_cast<uint32_t*>(g_Aq);
    int i = blockIdx.x * blockDim.x + threadIdx.x;
    int stride = gridDim.x * blockDim.x;
    for (; i < n4; i += stride) {
        float4 v = in[i];
        __nv_fp8x2_storage_t p0 = __nv_cvt_float2_to_fp8x2(
            make_float2(v.x * 0.5f, v.y * 0.5f), __NV_SATFINITE, __NV_E4M3);
        __nv_fp8x2_storage_t p1 = __nv_cvt_float2_to_fp8x2(
            make_float2(v.z * 0.5f, v.w * 0.5f), __NV_SATFINITE, __NV_E4M3);
        out[i] = (uint32_t)p0 | ((uint32_t)p1 << 16);
    }
}

// ============================================================================
// Kernel 2: weight dtype detect + normalize to e4m3 bytes
// ============================================================================
__global__ void detect_wdtype(const float* __restrict__ w) {
    if (blockIdx.x == 0 && threadIdx.x == 0) {
        int ok = 1;
        for (int i = 0; i < 256; i++) {
            float x = w[i];
            if (!(fabsf(x) <= 448.0f)) { ok = 0; break; }
        }
        g_wflag = ok;
    }
}

__global__ void prep_w(const void* __restrict__ w, int n) {
    int flag = g_wflag;
    int idx = blockIdx.x * blockDim.x + threadIdx.x;
    int stride = gridDim.x * blockDim.x;
    if (flag) {
        const float4* wf = (const float4*)w;
        uint32_t* o = reinterpret_cast<uint32_t*>(g_Wq);
        for (int i = idx; i < n / 4; i += stride) {
            float4 v = wf[i];
            __nv_fp8x2_storage_t p0 = __nv_cvt_float2_to_fp8x2(
                make_float2(v.x, v.y), __NV_SATFINITE, __NV_E4M3);
            __nv_fp8x2_storage_t p1 = __nv_cvt_float2_to_fp8x2(
                make_float2(v.z, v.w), __NV_SATFINITE, __NV_E4M3);
            o[i] = (uint32_t)p0 | ((uint32_t)p1 << 16);
        }
    } else {
        const uint4* wb = (const uint4*)w;
        uint4* o = reinterpret_cast<uint4*>(g_Wq);
        for (int i = idx; i < n / 16; i += stride) o[i] = wb[i];
    }
}

// ============================================================================
// Kernel 3: FP8 GEMM
//   CTA tile 256(M) x 128(N), BK = 128, 3-stage cp.async pipeline, 512 thr.
//   16 warps, warp tile 64x32 (wm 0..3 along M, wn 0..3 along N).
// ============================================================================
#define BM 256
#define BN 128
#define BK 128
#define KDIM 4096
#define NDIM 4096
#define MDIM 16384
#define KCHUNKS (KDIM / BK)          // 32
#define STAGES 3
#define NTHREADS 512

#define A_BYTES (BM * BK)            // 32768
#define B_BYTES (BN * BK)            // 16384
#define STAGE_BYTES (A_BYTES + B_BYTES)
#define SM_TOTAL (STAGES * STAGE_BYTES)   // 147456

DI void load_stage(uint32_t sb, int stage, const uint8_t* __restrict__ Ag,
                   const uint8_t* __restrict__ Bg, int ck, int tid) {
    uint32_t As = sb + stage * STAGE_BYTES;
    uint32_t Bs = As + A_BYTES;
    int col = tid & 7;            // 16B segment within 128B row
    int row0 = tid >> 3;          // 0..63
    const uint8_t* ag = Ag + (size_t)ck * BK + col * 16;
    const uint8_t* bg = Bg + (size_t)ck * BK + col * 16;
#pragma unroll
    for (int i = 0; i < BM / 64; i++) {
        int row = row0 + i * 64;
        cp_async16(As + swz(row, col), ag + (size_t)row * KDIM);
    }
#pragma unroll
    for (int i = 0; i < BN / 64; i++) {
        int row = row0 + i * 64;
        cp_async16(Bs + swz(row, col), bg + (size_t)row * KDIM);
    }
}

__global__ void __launch_bounds__(NTHREADS, 1)
gemm_kernel(const float* __restrict__ bias, float* __restrict__ out) {
    extern __shared__ char smem[];
    uint32_t sb = smem_u32(smem);
    int tid = (int)threadIdx.x;
    int wid = tid >> 5;
    int lid = tid & 31;
    int wm = wid & 3;                 // M dir: 4 warps * 64 rows
    int wn = wid >> 2;                // N dir: 4 warps * 32 cols
    int tm = blockIdx.y;              // M tile
    int tn = blockIdx.x;              // N tile

    const uint8_t* Ag = g_Aq + (size_t)tm * BM * KDIM;
    const uint8_t* Bg = g_Wq + (size_t)tn * BN * KDIM;

    float acc[4][4][4];
#pragma unroll
    for (int mi = 0; mi < 4; mi++)
#pragma unroll
        for (int ni = 0; ni < 4; ni++)
#pragma unroll
            for (int r = 0; r < 4; r++) acc[mi][ni][r] = 0.0f;

    // lane-derived ldmatrix source coordinates (proven in R2)
    int a_row_l = (lid & 7) + ((lid >> 3) & 1) * 8;   // 0..15 within m16 tile
    int a_half  = lid >> 4;                            // 16B half of k32
    int b_row_l = (lid & 7) + ((lid >> 4) & 1) * 8;   // 0..15 within n16 pair
    int b_half  = (lid >> 3) & 1;                      // 16B half of k32

    // prologue: stages 0,1
#pragma unroll
    for (int s = 0; s < STAGES - 1; s++) {
        load_stage(sb, s, Ag, Bg, s, tid);
        cp_commit();
    }

    for (int ck = 0; ck < KCHUNKS; ck++) {
        cp_wait<STAGES - 2>();            // stage ck resident
        __syncthreads();                  // protects arrived stage AND the
                                          // stage about to be overwritten
        int pf = ck + STAGES - 1;
        if (pf < KCHUNKS) load_stage(sb, pf % STAGES, Ag, Bg, pf, tid);
        cp_commit();                      // (possibly empty group: keeps
                                          //  wait_group accounting uniform)

        uint32_t As = sb + (ck % STAGES) * STAGE_BYTES;
        uint32_t Bs = As + A_BYTES;

#pragma unroll
        for (int ks = 0; ks < 4; ks++) {   // 4 x k32 within BK=128
            uint32_t a[4][4];
            uint32_t b[4][2];
#pragma unroll
            for (int mi = 0; mi < 4; mi++) {
                int row = wm * 64 + mi * 16 + a_row_l;
                int col16 = ks * 2 + a_half;
                ldmatrix4(a[mi][0], a[mi][1], a[mi][2], a[mi][3], As + swz(row, col16));
            }
#pragma unroll
            for (int np = 0; np < 2; np++) {
                int n = wn * 32 + np * 16 + b_row_l;
                int col16 = ks * 2 + b_half;
                ldmatrix4(b[2 * np][0], b[2 * np][1], b[2 * np + 1][0], b[2 * np + 1][1],
                          Bs + swz(n, col16));
            }
#pragma unroll
            for (int mi = 0; mi < 4; mi++)
#pragma unroll
                for (int ni = 0; ni < 4; ni++)
                    mma_e4m3(acc[mi][ni][0], acc[mi][ni][1], acc[mi][ni][2], acc[mi][ni][3],
                             a[mi][0], a[mi][1], a[mi][2], a[mi][3],
                             b[ni][0], b[ni][1]);
        }
    }

    // Epilogue: out = acc*4 + bias
    int qrow = lid >> 2;                 // 0..7
    int qcol = (lid & 3) * 2;            // 0,2,4,6
    int m0 = tm * BM + wm * 64 + qrow;
    int n0 = tn * BN + wn * 32 + qcol;
#pragma unroll
    for (int mi = 0; mi < 4; mi++) {
#pragma unroll
        for (int ni = 0; ni < 4; ni++) {
            int n = n0 + ni * 8;
            float b0 = __ldg(bias + n);
            float b1 = __ldg(bias + n + 1);
            int mA = m0 + mi * 16;
            int mB = mA + 8;
            float2 v0 = make_float2(acc[mi][ni][0] * 4.0f + b0,
                                    acc[mi][ni][1] * 4.0f + b1);
            float2 v1 = make_float2(acc[mi][ni][2] * 4.0f + b0,
                                    acc[mi][ni][3] * 4.0f + b1);
            *reinterpret_cast<float2*>(out + (size_t)mA * NDIM + n) = v0;
            *reinterpret_cast<float2*>(out + (size_t)mB * NDIM + n) = v1;
        }
    }
}

// ============================================================================
// Host launch
// ============================================================================
extern "C" void kernel_launch(void* const* d_in, const int* in_sizes, int n_in,
                              void* d_out, int out_size) {
    const float* input = nullptr;
    const void*  weight = nullptr;
    const float* bias = nullptr;
    for (int i = 0; i < n_in; i++) {
        if (in_sizes[i] == 4 * 4096 * 4096)  input = (const float*)d_in[i];
        else if (in_sizes[i] == 4096 * 4096) weight = d_in[i];
        else if (in_sizes[i] == 4096)        bias = (const float*)d_in[i];
    }
    if (!input)  input  = (const float*)d_in[0];
    if (!weight) weight = d_in[1];
    if (!bias)   bias   = (const float*)d_in[2];
    float* out = (float*)d_out;

    // 1) quantize activations
    int n4 = (4 * 4096 * 4096) / 4;
    quant_act<<<8192, 256>>>((const float4*)input, n4);

    // 2) weight dtype detect + normalize to e4m3 bytes
    detect_wdtype<<<1, 1>>>((const float*)weight);
    prep_w<<<2048, 256>>>(weight, 4096 * 4096);

    // 3) GEMM + epilogue
    static bool attr_set = false;
    if (!attr_set) {
        cudaFuncSetAttribute(gemm_kernel,
                             cudaFuncAttributeMaxDynamicSharedMemorySize, SM_TOTAL);
        attr_set = true;
    }
    dim3 grid(NDIM / BN, MDIM / BM);   // (32, 64)
    gemm_kernel<<<grid, NTHREADS, SM_TOTAL>>>(bias, out);
}

// round 4
// speedup vs baseline: 1.1991x; 1.0292x over previous
#include <cuda_runtime.h>
#include <cuda_fp8.h>
#include <cstdint>

// ============================================================================
// y[b,s,o] = 4 * sum_i e4m3(x[b,s,i]*0.5) * W_e4m3[o,i]  + bias[o]
// M = 16384, N = 4096, K = 4096, fp32 out.
// R4: CTA 128x128, 256 thr, 2 CTAs/SM (decoupled barriers), BK=128, 3 stages,
//     fragment double-buffering + XOR swizzle addressing.
// ============================================================================

#define DI __device__ __forceinline__

// ---------------- device scratch --------------------------------------------
__device__ uint8_t g_Aq[16384u * 4096u];   // 64MB quantized activations (e4m3)
__device__ uint8_t g_Wq[4096u * 4096u];    // 16MB weight as e4m3 bytes
__device__ int     g_wflag;                // 1 if weight buffer is fp32

// ---------------- helpers ---------------------------------------------------
DI uint32_t smem_u32(const void* p) {
    uint32_t a;
    asm("{ .reg .u64 t; cvta.to.shared.u64 t, %1; cvt.u32.u64 %0, t; }"
        : "=r"(a) : "l"(p));
    return a;
}
DI void cp_async16(uint32_t dst, const void* src) {
    asm volatile("cp.async.cg.shared.global [%0], [%1], 16;" :: "r"(dst), "l"(src));
}
DI void cp_commit() { asm volatile("cp.async.commit_group;" ::: "memory"); }
template <int N> DI void cp_wait() {
    asm volatile("cp.async.wait_group %0;" :: "n"(N) : "memory");
}
DI void ldmatrix4(uint32_t& r0, uint32_t& r1, uint32_t& r2, uint32_t& r3, uint32_t a) {
    asm volatile("ldmatrix.sync.aligned.m8n8.x4.shared.b16 {%0,%1,%2,%3}, [%4];"
                 : "=r"(r0), "=r"(r1), "=r"(r2), "=r"(r3) : "r"(a));
}
DI void mma_e4m3(float& c0, float& c1, float& c2, float& c3,
                 uint32_t a0, uint32_t a1, uint32_t a2, uint32_t a3,
                 uint32_t b0, uint32_t b1) {
    asm volatile(
        "mma.sync.aligned.m16n8k32.row.col.f32.e4m3.e4m3.f32 "
        "{%0,%1,%2,%3}, {%4,%5,%6,%7}, {%8,%9}, {%0,%1,%2,%3};"
        : "+f"(c0), "+f"(c1), "+f"(c2), "+f"(c3)
        : "r"(a0), "r"(a1), "r"(a2), "r"(a3), "r"(b0), "r"(b1));
}

// 128B rows, 8 x 16B units: addr = row*128 + ((col16 ^ (row&7))<<4).
// XOR algebra (no carries): addr(ks) = base ^ (ks<<5), with
// base = row*128 + ((half ^ (row&7))<<4) and col16 = ks*2 + half.
DI uint32_t swz(int row, int col16) {
    return (uint32_t)(row * 128 + ((col16 ^ (row & 7)) << 4));
}

// ============================================================================
// Kernel 1: quantize activations  e4m3(x * 0.5)
// ============================================================================
__global__ void quant_act(const float4* __restrict__ in, int n4) {
    uint32_t* out = reinterpret_cast<uint32_t*>(g_Aq);
    int i = blockIdx.x * blockDim.x + threadIdx.x;
    int stride = gridDim.x * blockDim.x;
    for (; i < n4; i += stride) {
        float4 v = in[i];
        __nv_fp8x2_storage_t p0 = __nv_cvt_float2_to_fp8x2(
            make_float2(v.x * 0.5f, v.y * 0.5f), __NV_SATFINITE, __NV_E4M3);
        __nv_fp8x2_storage_t p1 = __nv_cvt_float2_to_fp8x2(
            make_float2(v.z * 0.5f, v.w * 0.5f), __NV_SATFINITE, __NV_E4M3);
        out[i] = (uint32_t)p0 | ((uint32_t)p1 << 16);
    }
}

// ============================================================================
// Kernel 2: weight dtype detect + normalize to e4m3 bytes
// ============================================================================
__global__ void detect_wdtype(const float* __restrict__ w) {
    if (blockIdx.x == 0 && threadIdx.x == 0) {
        int ok = 1;
        for (int i = 0; i < 256; i++) {
            float x = w[i];
            if (!(fabsf(x) <= 448.0f)) { ok = 0; break; }
        }
        g_wflag = ok;
    }
}

__global__ void prep_w(const void* __restrict__ w, int n) {
    int flag = g_wflag;
    int idx = blockIdx.x * blockDim.x + threadIdx.x;
    int stride = gridDim.x * blockDim.x;
    if (flag) {
        const float4* wf = (const float4*)w;
        uint32_t* o = reinterpret_cast<uint32_t*>(g_Wq);
        for (int i = idx; i < n / 4; i += stride) {
            float4 v = wf[i];
            __nv_fp8x2_storage_t p0 = __nv_cvt_float2_to_fp8x2(
                make_float2(v.x, v.y), __NV_SATFINITE, __NV_E4M3);
            __nv_fp8x2_storage_t p1 = __nv_cvt_float2_to_fp8x2(
                make_float2(v.z, v.w), __NV_SATFINITE, __NV_E4M3);
            o[i] = (uint32_t)p0 | ((uint32_t)p1 << 16);
        }
    } else {
        const uint4* wb = (const uint4*)w;
        uint4* o = reinterpret_cast<uint4*>(g_Wq);
        for (int i = idx; i < n / 16; i += stride) o[i] = wb[i];
    }
}

// ============================================================================
// Kernel 3: FP8 GEMM
//   CTA tile 128(M) x 128(N), BK = 128, 3-stage cp.async pipeline, 256 thr.
//   8 warps: wm = wid&1 (2 x 64 rows), wn = wid>>1 (4 x 32 cols).
//   2 CTAs per SM for decoupled-barrier latency hiding.
// ============================================================================
#define BM 128
#define BN 128
#define BK 128
#define KDIM 4096
#define NDIM 4096
#define MDIM 16384
#define KCHUNKS (KDIM / BK)          // 32
#define STAGES 3
#define NTHREADS 256

#define A_BYTES (BM * BK)            // 16384
#define B_BYTES (BN * BK)            // 16384
#define STAGE_BYTES (A_BYTES + B_BYTES)   // 32768
#define SM_TOTAL (STAGES * STAGE_BYTES)   // 98304 per CTA

DI void load_stage(uint32_t sb, int stage, const uint8_t* __restrict__ Ag,
                   const uint8_t* __restrict__ Bg, int ck, int tid) {
    uint32_t As = sb + stage * STAGE_BYTES;
    uint32_t Bs = As + A_BYTES;
    int col = tid & 7;            // 16B segment within 128B row
    int row0 = tid >> 3;          // 0..31
    const uint8_t* ag = Ag + (size_t)ck * BK + col * 16;
    const uint8_t* bg = Bg + (size_t)ck * BK + col * 16;
#pragma unroll
    for (int i = 0; i < BM / 32; i++) {
        int row = row0 + i * 32;
        cp_async16(As + swz(row, col), ag + (size_t)row * KDIM);
    }
#pragma unroll
    for (int i = 0; i < BN / 32; i++) {
        int row = row0 + i * 32;
        cp_async16(Bs + swz(row, col), bg + (size_t)row * KDIM);
    }
}

__global__ void __launch_bounds__(NTHREADS, 2)
gemm_kernel(const float* __restrict__ bias, float* __restrict__ out) {
    extern __shared__ char smem[];
    uint32_t sb = smem_u32(smem);
    int tid = (int)threadIdx.x;
    int wid = tid >> 5;
    int lid = tid & 31;
    int wm = wid & 1;                 // M dir: 2 warps * 64 rows
    int wn = wid >> 1;                // N dir: 4 warps * 32 cols
    int tm = blockIdx.y;              // M tile
    int tn = blockIdx.x;              // N tile

    const uint8_t* Ag = g_Aq + (size_t)tm * BM * KDIM;
    const uint8_t* Bg = g_Wq + (size_t)tn * BN * KDIM;

    float acc[4][4][4];
#pragma unroll
    for (int mi = 0; mi < 4; mi++)
#pragma unroll
        for (int ni = 0; ni < 4; ni++)
#pragma unroll
            for (int r = 0; r < 4; r++) acc[mi][ni][r] = 0.0f;

    // lane-derived ldmatrix source coordinates (proven R2/R3)
    int a_row_l = (lid & 7) + ((lid >> 3) & 1) * 8;   // 0..15 within m16 tile
    int a_half  = lid >> 4;                            // 16B half of k32
    int b_row_l = (lid & 7) + ((lid >> 4) & 1) * 8;   // 0..15 within n16 pair
    int b_half  = (lid >> 3) & 1;                      // 16B half of k32

    // per-lane XOR-base offsets (stage-independent part)
    uint32_t aOff[4], bOff[2];
#pragma unroll
    for (int mi = 0; mi < 4; mi++) {
        int row = wm * 64 + mi * 16 + a_row_l;
        aOff[mi] = (uint32_t)(row * 128 + ((a_half ^ (row & 7)) << 4));
    }
#pragma unroll
    for (int np = 0; np < 2; np++) {
        int n = wn * 32 + np * 16 + b_row_l;
        bOff[np] = (uint32_t)(n * 128 + ((b_half ^ (n & 7)) << 4));
    }

    // prologue: stages 0,1
#pragma unroll
    for (int s = 0; s < STAGES - 1; s++) {
        load_stage(sb, s, Ag, Bg, s, tid);
        cp_commit();
    }

    uint32_t a[2][4][4];
    uint32_t b[2][4][2];

    for (int ck = 0; ck < KCHUNKS; ck++) {
        cp_wait<STAGES - 2>();
        __syncthreads();
        int pf = ck + STAGES - 1;
        if (pf < KCHUNKS) {
            int s = pf;  // stage index = pf % STAGES
            s = (s >= STAGES) ? ((s >= 2 * STAGES) ? s % STAGES : s - STAGES) : s;
            load_stage(sb, s, Ag, Bg, pf, tid);
        }
        cp_commit();

        int cs = ck % STAGES;
        uint32_t As = sb + cs * STAGE_BYTES;
        uint32_t Bs = As + A_BYTES;
        uint32_t aB[4], bB[2];
#pragma unroll
        for (int mi = 0; mi < 4; mi++) aB[mi] = As + aOff[mi];
#pragma unroll
        for (int np = 0; np < 2; np++) bB[np] = Bs + bOff[np];

        // preload ks = 0 fragments
#pragma unroll
        for (int mi = 0; mi < 4; mi++)
            ldmatrix4(a[0][mi][0], a[0][mi][1], a[0][mi][2], a[0][mi][3], aB[mi]);
#pragma unroll
        for (int np = 0; np < 2; np++)
            ldmatrix4(b[0][2 * np][0], b[0][2 * np][1],
                      b[0][2 * np + 1][0], b[0][2 * np + 1][1], bB[np]);

#pragma unroll
        for (int ks = 0; ks < 4; ks++) {
            int cur = ks & 1;
            int nxt = cur ^ 1;
            if (ks < 3) {
                uint32_t x = (uint32_t)((ks + 1) << 5);
#pragma unroll
                for (int mi = 0; mi < 4; mi++)
                    ldmatrix4(a[nxt][mi][0], a[nxt][mi][1], a[nxt][mi][2], a[nxt][mi][3],
                              aB[mi] ^ x);
#pragma unroll
                for (int np = 0; np < 2; np++)
                    ldmatrix4(b[nxt][2 * np][0], b[nxt][2 * np][1],
                              b[nxt][2 * np + 1][0], b[nxt][2 * np + 1][1],
                              bB[np] ^ x);
            }
#pragma unroll
            for (int mi = 0; mi < 4; mi++)
#pragma unroll
                for (int ni = 0; ni < 4; ni++)
                    mma_e4m3(acc[mi][ni][0], acc[mi][ni][1], acc[mi][ni][2], acc[mi][ni][3],
                             a[cur][mi][0], a[cur][mi][1], a[cur][mi][2], a[cur][mi][3],
                             b[cur][ni][0], b[cur][ni][1]);
        }
    }

    // Epilogue: out = acc*4 + bias
    int qrow = lid >> 2;                 // 0..7
    int qcol = (lid & 3) * 2;            // 0,2,4,6
    int m0 = tm * BM + wm * 64 + qrow;
    int n0 = tn * BN + wn * 32 + qcol;
#pragma unroll
    for (int mi = 0; mi < 4; mi++) {
#pragma unroll
        for (int ni = 0; ni < 4; ni++) {
            int n = n0 + ni * 8;
            float b0 = __ldg(bias + n);
            float b1 = __ldg(bias + n + 1);
            int mA = m0 + mi * 16;
            int mB = mA + 8;
            float2 v0 = make_float2(acc[mi][ni][0] * 4.0f + b0,
                                    acc[mi][ni][1] * 4.0f + b1);
            float2 v1 = make_float2(acc[mi][ni][2] * 4.0f + b0,
                                    acc[mi][ni][3] * 4.0f + b1);
            *reinterpret_cast<float2*>(out + (size_t)mA * NDIM + n) = v0;
            *reinterpret_cast<float2*>(out + (size_t)mB * NDIM + n) = v1;
        }
    }
}

// ============================================================================
// Host launch
// ============================================================================
extern "C" void kernel_launch(void* const* d_in, const int* in_sizes, int n_in,
                              void* d_out, int out_size) {
    const float* input = nullptr;
    const void*  weight = nullptr;
    const float* bias = nullptr;
    for (int i = 0; i < n_in; i++) {
        if (in_sizes[i] == 4 * 4096 * 4096)  input = (const float*)d_in[i];
        else if (in_sizes[i] == 4096 * 4096) weight = d_in[i];
        else if (in_sizes[i] == 4096)        bias = (const float*)d_in[i];
    }
    if (!input)  input  = (const float*)d_in[0];
    if (!weight) weight = d_in[1];
    if (!bias)   bias   = (const float*)d_in[2];
    float* out = (float*)d_out;

    // 1) quantize activations
    int n4 = (4 * 4096 * 4096) / 4;
    quant_act<<<8192, 256>>>((const float4*)input, n4);

    // 2) weight dtype detect + normalize to e4m3 bytes
    detect_wdtype<<<1, 1>>>((const float*)weight);
    prep_w<<<2048, 256>>>(weight, 4096 * 4096);

    // 3) GEMM + epilogue
    static bool attr_set = false;
    if (!attr_set) {
        cudaFuncSetAttribute(gemm_kernel,
                             cudaFuncAttributeMaxDynamicSharedMemorySize, SM_TOTAL);
        attr_set = true;
    }
    dim3 grid(NDIM / BN, MDIM / BM);   // (32, 128)
    gemm_kernel<<<grid, NTHREADS, SM_TOTAL>>>(bias, out);
}